// round 11
// baseline (speedup 1.0000x reference)
#include <cuda_runtime.h>
#include <cuda_fp16.h>
#include <math.h>
#include <stdint.h>

#define HID    512
#define BATCH  4096
#define TSTEPS 20

// ---------------- fused_igo tiling (round-9 best: 128x128, 512 thr, 3-stage) --
#define BM 128
#define BN 128
#define BKE 64
#define SKB 144                         // padded smem row stride (bytes)
#define TILE_B (128 * SKB)              // 18432
#define F_STAGE_B (4 * TILE_B)          // 73728
#define F_SMEM (3 * F_STAGE_B)          // 221184

// ---------------- wout_update tiling: 32 rows x full N=512 --------------------
#define BM2 32
#define A2_B (32 * SKB)                 // 4608
#define B2_B (512 * SKB)                // 73728
#define U_STAGE_B (A2_B + B2_B)         // 78336
#define U_SMEM (2 * U_STAGE_B)          // 156672

// ---------------- scratch ----------------------------------------------------
__device__ __align__(16) float   g_z  [BATCH * HID];
__device__ __align__(16) __half  g_zh [BATCH * HID];
__device__ __align__(16) __half  g_dhh[BATCH * HID];
__device__ __align__(16) __half  g_wh [4][HID * HID];   // Wi, Wg, Wo, Wout (fp16)

// ---------------- helpers ----------------------------------------------------
static __device__ __forceinline__ uint32_t smem_u32(const void* p) {
    uint32_t a;
    asm("{ .reg .u64 t; cvta.to.shared.u64 t, %1; cvt.u32.u64 %0, t; }" : "=r"(a) : "l"(p));
    return a;
}
#define CP16(dst, src) \
    asm volatile("cp.async.cg.shared.global [%0], [%1], 16;" :: "r"(dst), "l"(src))
#define CPC()  asm volatile("cp.async.commit_group;" ::: "memory")
#define CPW1() asm volatile("cp.async.wait_group 1;" ::: "memory")
#define CPW0() asm volatile("cp.async.wait_group 0;" ::: "memory")

__device__ __forceinline__ void ldm4(uint32_t a, uint32_t& r0, uint32_t& r1,
                                     uint32_t& r2, uint32_t& r3) {
    asm volatile("ldmatrix.sync.aligned.m8n8.x4.shared.b16 {%0,%1,%2,%3}, [%4];"
                 : "=r"(r0), "=r"(r1), "=r"(r2), "=r"(r3) : "r"(a));
}
__device__ __forceinline__ void mma_f16(uint32_t* c, const uint32_t* a, uint32_t b0, uint32_t b1) {
    asm volatile("mma.sync.aligned.m16n8k16.row.col.f16.f16.f16.f16 "
                 "{%0,%1},{%2,%3,%4,%5},{%6,%7},{%0,%1};"
                 : "+r"(c[0]), "+r"(c[1])
                 : "r"(a[0]), "r"(a[1]), "r"(a[2]), "r"(a[3]), "r"(b0), "r"(b1));
}
__device__ __forceinline__ float fsig(float x)  { return __fdividef(1.f, 1.f + __expf(-x)); }
__device__ __forceinline__ float ftanh(float x) { return __fdividef(2.f, 1.f + __expf(-2.f * x)) - 1.f; }

// ---------------- setup ------------------------------------------------------
__global__ void w2h_kernel(const float* __restrict__ Wi, const float* __restrict__ Wg,
                           const float* __restrict__ Wo, const float* __restrict__ Wout) {
    int i = blockIdx.x * blockDim.x + threadIdx.x;
    if (i >= 4 * HID * HID) return;
    int m = i >> 18, r = i & (HID * HID - 1);
    const float* src = (m == 0) ? Wi : (m == 1) ? Wg : (m == 2) ? Wo : Wout;
    g_wh[m][r] = __float2half_rn(src[r]);
}

__global__ void copy_z_kernel(const float* __restrict__ y) {
    int i = blockIdx.x * blockDim.x + threadIdx.x;
    if (i < BATCH * HID) { float v = y[i]; g_z[i] = v; g_zh[i] = __float2half_rn(v); }
}

// ---------------- fused_igo cp.async issuer (512 threads, 3 stages) ----------
__device__ __forceinline__ void f_issue(uint32_t sb, int tid, int bm, int bn, int ch, int stage) {
    const uint32_t base = sb + (uint32_t)stage * F_STAGE_B;
    const int k0 = ch * BKE;
    #pragma unroll
    for (int i = 0; i < 8; ++i) {
        int idx = i * 512 + tid;              // 0..4095 segments of 16B
        int tl = idx >> 10, r = (idx >> 3) & 127, c = idx & 7;
        const __half* src = (tl == 0)
            ? (g_zh + (bm + r) * HID + k0 + c * 8)
            : (g_wh[tl - 1] + (bn + r) * HID + k0 + c * 8);
        uint32_t dst = base + (uint32_t)(tl * TILE_B + r * SKB + c * 16);
        CP16(dst, src);
    }
    CPC();
}

// ---------------- fused i/g/o HMMA GEMM (128x128, 16 warps, f16 acc) ---------
__global__ __launch_bounds__(512, 1) void fused_igo_mma() {
    extern __shared__ __half sm[];
    const uint32_t sb = smem_u32(sm);
    const int tid = threadIdx.x, lane = tid & 31, wid = tid >> 5;
    const int warpM = wid & 3, warpN = wid >> 2;
    const int bm = blockIdx.x * BM, bn = blockIdx.y * BN;

    uint32_t acc[3][2][4][2];
    #pragma unroll
    for (int w = 0; w < 3; ++w)
        #pragma unroll
        for (int mi = 0; mi < 2; ++mi)
            #pragma unroll
            for (int ni = 0; ni < 4; ++ni) { acc[w][mi][ni][0] = 0u; acc[w][mi][ni][1] = 0u; }

    const int am = warpM * 32 + (lane & 15);
    const int akb = (lane >> 4) << 4;
    const int brow0 = warpN * 32 + ((lane >> 4) << 3) + (lane & 7);
    const int bkb = ((lane >> 3) & 1) << 4;

    f_issue(sb, tid, bm, bn, 0, 0);
    f_issue(sb, tid, bm, bn, 1, 1);

    int stage = 0;
    #pragma unroll 1
    for (int ch = 0; ch < HID / BKE; ++ch) {
        if (ch < HID / BKE - 1) { CPW1(); } else { CPW0(); }
        __syncthreads();
        if (ch + 2 < HID / BKE) {
            int ns = stage + 2; if (ns >= 3) ns -= 3;
            f_issue(sb, tid, bm, bn, ch + 2, ns);
        }
        const uint32_t base = sb + (uint32_t)stage * F_STAGE_B;
        #pragma unroll
        for (int kk = 0; kk < BKE; kk += 16) {
            uint32_t fa[2][4];
            uint32_t aadr = base + (uint32_t)(am * SKB + kk * 2 + akb);
            ldm4(aadr,            fa[0][0], fa[0][1], fa[0][2], fa[0][3]);
            ldm4(aadr + 16 * SKB, fa[1][0], fa[1][1], fa[1][2], fa[1][3]);
            #pragma unroll
            for (int w = 0; w < 3; ++w) {
                const uint32_t wb = base + (uint32_t)((w + 1) * TILE_B) + (uint32_t)(kk * 2 + bkb);
                #pragma unroll
                for (int g = 0; g < 2; ++g) {
                    uint32_t b0, b1, b2, b3;
                    ldm4(wb + (uint32_t)((brow0 + g * 16) * SKB), b0, b1, b2, b3);
                    mma_f16(acc[w][0][2 * g + 0], fa[0], b0, b1);
                    mma_f16(acc[w][0][2 * g + 1], fa[0], b2, b3);
                    mma_f16(acc[w][1][2 * g + 0], fa[1], b0, b1);
                    mma_f16(acc[w][1][2 * g + 1], fa[1], b2, b3);
                }
            }
        }
        if (++stage >= 3) stage -= 3;
    }

    #pragma unroll
    for (int mi = 0; mi < 2; ++mi) {
        #pragma unroll
        for (int rr = 0; rr < 2; ++rr) {
            const int r = bm + warpM * 32 + mi * 16 + rr * 8 + (lane >> 2);
            #pragma unroll
            for (int ni = 0; ni < 4; ++ni) {
                const int col = bn + warpN * 32 + ni * 8 + ((lane & 3) << 1);
                float2 pi = __half22float2(*(__half2*)&acc[0][mi][ni][rr]);
                float2 pg = __half22float2(*(__half2*)&acc[1][mi][ni][rr]);
                float2 po = __half22float2(*(__half2*)&acc[2][mi][ni][rr]);
                float d0 = fsig(po.x) * ftanh(fsig(pi.x) * ftanh(pg.x));
                float d1 = fsig(po.y) * ftanh(fsig(pi.y) * ftanh(pg.y));
                *(__half2*)(g_dhh + r * HID + col) = __floats2half2_rn(d0, d1);
            }
        }
    }
}

// ---------------- wout_update: GEMM(32xHID) + softmax-z-update + readout -----
// s = dh[bm:bm+32] @ Wout^T + bout   (full rows per CTA)
// z += dt*softmax(s);  out[:, t+1] = softmax(z_new).Wfc + bfc
__device__ __forceinline__ void u_issue(uint32_t sb, int tid, int bm, int ch, int stage) {
    const uint32_t base = sb + (uint32_t)stage * U_STAGE_B;
    const int k0 = ch * BKE;
    #pragma unroll
    for (int i = 0; i < 17; ++i) {
        int idx = i * 256 + tid;              // 0..4351 segments of 16B
        uint32_t dst; const __half* src;
        if (idx < 256) {                      // A: 32 rows x 8 segs
            int r = idx >> 3, c = idx & 7;
            dst = base + (uint32_t)(r * SKB + c * 16);
            src = g_dhh + (bm + r) * HID + k0 + c * 8;
        } else {                              // B: 512 rows x 8 segs (all of Wout)
            int ib = idx - 256;
            int r = ib >> 3, c = ib & 7;
            dst = base + (uint32_t)(A2_B + r * SKB + c * 16);
            src = g_wh[3] + r * HID + k0 + c * 8;
        }
        CP16(dst, src);
    }
    CPC();
}

__global__ __launch_bounds__(256, 1) void wout_update(
    const float* __restrict__ bout, const float* __restrict__ ts,
    const float* __restrict__ Wfc, const float* __restrict__ bfc,
    float* __restrict__ out, int t)
{
    extern __shared__ __half sm[];
    const uint32_t sb = smem_u32(sm);
    const int tid = threadIdx.x, lane = tid & 31, wid = tid >> 5;
    const int bm = blockIdx.x * BM2;

    uint32_t acc[2][8][2];                    // [mi][ni][rr], warp cols = wid*64..+63
    #pragma unroll
    for (int mi = 0; mi < 2; ++mi)
        #pragma unroll
        for (int ni = 0; ni < 8; ++ni) { acc[mi][ni][0] = 0u; acc[mi][ni][1] = 0u; }

    const int am = lane & 15;
    const int akb = (lane >> 4) << 4;
    const int brow0 = wid * 64 + ((lane >> 4) << 3) + (lane & 7);
    const int bkb = ((lane >> 3) & 1) << 4;

    u_issue(sb, tid, bm, 0, 0);
    #pragma unroll 1
    for (int ch = 0; ch < HID / BKE; ++ch) {
        if (ch < HID / BKE - 1) { u_issue(sb, tid, bm, ch + 1, (ch + 1) & 1); CPW1(); }
        else                    { CPW0(); }
        __syncthreads();
        const uint32_t base = sb + (uint32_t)(ch & 1) * U_STAGE_B;
        #pragma unroll
        for (int kk = 0; kk < BKE; kk += 16) {
            uint32_t fa[2][4];
            uint32_t aadr = base + (uint32_t)(am * SKB + kk * 2 + akb);
            ldm4(aadr,            fa[0][0], fa[0][1], fa[0][2], fa[0][3]);
            ldm4(aadr + 16 * SKB, fa[1][0], fa[1][1], fa[1][2], fa[1][3]);
            #pragma unroll
            for (int g = 0; g < 4; ++g) {
                uint32_t b0, b1, b2, b3;
                ldm4(base + (uint32_t)(A2_B + (brow0 + g * 16) * SKB) + (uint32_t)(kk * 2 + bkb),
                     b0, b1, b2, b3);
                mma_f16(acc[0][2 * g + 0], fa[0], b0, b1);
                mma_f16(acc[0][2 * g + 1], fa[0], b2, b3);
                mma_f16(acc[1][2 * g + 0], fa[1], b0, b1);
                mma_f16(acc[1][2 * g + 1], fa[1], b2, b3);
            }
        }
        __syncthreads();
    }

    // ---- epilogue: row softmax of s over full HID, z update, readout ----
    float* red1  = (float*)sm;                // [8][32]
    float* red2  = red1 + 256;                // [8][32]
    float* rowb1 = red2 + 256;                // [32]
    float* rowb2 = rowb1 + 32;                // [32]

    // bias values for this lane's 16 columns
    float bv[16];
    #pragma unroll
    for (int ni = 0; ni < 8; ++ni) {
        const int col = wid * 64 + ni * 8 + ((lane & 3) << 1);
        float2 b = *(const float2*)(bout + col);
        bv[2 * ni] = b.x; bv[2 * ni + 1] = b.y;
    }
    const float dt = ts[t + 1] - ts[t];
    const float bf0 = bfc[0];

    // pass 1: row max of s
    #pragma unroll
    for (int q = 0; q < 4; ++q) {
        const int mi = q >> 1, rr = q & 1;
        const int rloc = mi * 16 + rr * 8 + (lane >> 2);
        float m = -1e30f;
        #pragma unroll
        for (int ni = 0; ni < 8; ++ni) {
            float2 v = __half22float2(*(__half2*)&acc[mi][ni][rr]);
            m = fmaxf(m, fmaxf(v.x + bv[2 * ni], v.y + bv[2 * ni + 1]));
        }
        m = fmaxf(m, __shfl_xor_sync(0xffffffffu, m, 1));
        m = fmaxf(m, __shfl_xor_sync(0xffffffffu, m, 2));
        if ((lane & 3) == 0) red1[wid * 32 + rloc] = m;
    }
    __syncthreads();
    if (tid < 32) {
        float m = red1[tid];
        #pragma unroll
        for (int w = 1; w < 8; ++w) m = fmaxf(m, red1[w * 32 + tid]);
        rowb1[tid] = m;
    }
    __syncthreads();

    // pass 2: sum of exp
    float rmax[4];
    #pragma unroll
    for (int q = 0; q < 4; ++q) {
        const int mi = q >> 1, rr = q & 1;
        const int rloc = mi * 16 + rr * 8 + (lane >> 2);
        rmax[q] = rowb1[rloc];
        float s = 0.f;
        #pragma unroll
        for (int ni = 0; ni < 8; ++ni) {
            float2 v = __half22float2(*(__half2*)&acc[mi][ni][rr]);
            s += __expf(v.x + bv[2 * ni] - rmax[q]) + __expf(v.y + bv[2 * ni + 1] - rmax[q]);
        }
        s += __shfl_xor_sync(0xffffffffu, s, 1);
        s += __shfl_xor_sync(0xffffffffu, s, 2);
        if ((lane & 3) == 0) red2[wid * 32 + rloc] = s;
    }
    __syncthreads();
    if (tid < 32) {
        float s = red2[tid];
        #pragma unroll
        for (int w = 1; w < 8; ++w) s += red2[w * 32 + tid];
        rowb2[tid] = s;
    }
    __syncthreads();

    // pass 3: z update + max of z_new
    #pragma unroll
    for (int q = 0; q < 4; ++q) {
        const int mi = q >> 1, rr = q & 1;
        const int rloc = mi * 16 + rr * 8 + (lane >> 2);
        const int grow = bm + rloc;
        const float scl = __fdividef(dt, rowb2[rloc]);
        float zm = -1e30f;
        #pragma unroll
        for (int ni = 0; ni < 8; ++ni) {
            const int col = wid * 64 + ni * 8 + ((lane & 3) << 1);
            float2 v = __half22float2(*(__half2*)&acc[mi][ni][rr]);
            float2 zo = *(const float2*)(g_z + grow * HID + col);
            float zn0 = zo.x + __expf(v.x + bv[2 * ni]     - rmax[q]) * scl;
            float zn1 = zo.y + __expf(v.y + bv[2 * ni + 1] - rmax[q]) * scl;
            float2 zn = { zn0, zn1 };
            *(float2*)(g_z + grow * HID + col) = zn;
            *(__half2*)(g_zh + grow * HID + col) = __floats2half2_rn(zn0, zn1);
            zm = fmaxf(zm, fmaxf(zn0, zn1));
        }
        zm = fmaxf(zm, __shfl_xor_sync(0xffffffffu, zm, 1));
        zm = fmaxf(zm, __shfl_xor_sync(0xffffffffu, zm, 2));
        if ((lane & 3) == 0) red1[wid * 32 + rloc] = zm;
    }
    __syncthreads();
    if (tid < 32) {
        float m = red1[tid];
        #pragma unroll
        for (int w = 1; w < 8; ++w) m = fmaxf(m, red1[w * 32 + tid]);
        rowb1[tid] = m;
    }
    __syncthreads();

    // pass 4: softmax(z_new) sum + dot with Wfc
    #pragma unroll
    for (int q = 0; q < 4; ++q) {
        const int mi = q >> 1, rr = q & 1;
        const int rloc = mi * 16 + rr * 8 + (lane >> 2);
        const int grow = bm + rloc;
        const float zmax = rowb1[rloc];
        float zs = 0.f, zd = 0.f;
        #pragma unroll
        for (int ni = 0; ni < 8; ++ni) {
            const int col = wid * 64 + ni * 8 + ((lane & 3) << 1);
            float2 zn = *(const float2*)(g_z + grow * HID + col);
            float2 wf = *(const float2*)(Wfc + col);
            float e0 = __expf(zn.x - zmax), e1 = __expf(zn.y - zmax);
            zs += e0 + e1;
            zd += e0 * wf.x + e1 * wf.y;
        }
        zs += __shfl_xor_sync(0xffffffffu, zs, 1);
        zs += __shfl_xor_sync(0xffffffffu, zs, 2);
        zd += __shfl_xor_sync(0xffffffffu, zd, 1);
        zd += __shfl_xor_sync(0xffffffffu, zd, 2);
        if ((lane & 3) == 0) { red1[wid * 32 + rloc] = zs; red2[wid * 32 + rloc] = zd; }
    }
    __syncthreads();
    if (tid < 32) {
        float zs = red1[tid], zd = red2[tid];
        #pragma unroll
        for (int w = 1; w < 8; ++w) { zs += red1[w * 32 + tid]; zd += red2[w * 32 + tid]; }
        out[(bm + tid) * TSTEPS + t + 1] = __fdividef(zd, zs) + bf0;
    }
}

// out[b, 0] = softmax_row(z[b]) . Wfc + bfc
__global__ __launch_bounds__(256) void softmaxdot_kernel(
    const float* __restrict__ Wfc, const float* __restrict__ bfc,
    float* __restrict__ out)
{
    const int b = blockIdx.x;
    const int tid = threadIdx.x;
    float v0 = g_z[b * HID + tid], v1 = g_z[b * HID + tid + 256];
    __shared__ float red_s[8], red_d[8];

    float m = fmaxf(v0, v1);
    #pragma unroll
    for (int o = 16; o; o >>= 1) m = fmaxf(m, __shfl_xor_sync(0xffffffffu, m, o));
    if ((tid & 31) == 0) red_s[tid >> 5] = m;
    __syncthreads();
    if (tid == 0) {
        float mm = red_s[0];
        #pragma unroll
        for (int i = 1; i < 8; ++i) mm = fmaxf(mm, red_s[i]);
        red_s[0] = mm;
    }
    __syncthreads();
    m = red_s[0];
    __syncthreads();
    float e0 = __expf(v0 - m), e1 = __expf(v1 - m);
    float s = e0 + e1;
    float d = e0 * Wfc[tid] + e1 * Wfc[tid + 256];
    #pragma unroll
    for (int o = 16; o; o >>= 1) {
        s += __shfl_xor_sync(0xffffffffu, s, o);
        d += __shfl_xor_sync(0xffffffffu, d, o);
    }
    if ((tid & 31) == 0) { red_s[tid >> 5] = s; red_d[tid >> 5] = d; }
    __syncthreads();
    if (tid == 0) {
        float ss = 0.f, dd = 0.f;
        #pragma unroll
        for (int i = 0; i < 8; ++i) { ss += red_s[i]; dd += red_d[i]; }
        out[b * TSTEPS + 0] = __fdividef(dd, ss) + bfc[0];
    }
}

// ---------------- launch -----------------------------------------------------
extern "C" void kernel_launch(void* const* d_in, const int* in_sizes, int n_in,
                              void* d_out, int out_size) {
    const float* y    = (const float*)d_in[0];
    const float* ts   = (const float*)d_in[1];
    const float* Wi   = (const float*)d_in[2];
    // d_in[3] = Wf — dead in the reference (f computed but unused), skipped.
    const float* Wg   = (const float*)d_in[4];
    const float* Wo   = (const float*)d_in[5];
    const float* Wout = (const float*)d_in[6];
    const float* bout = (const float*)d_in[7];
    const float* Wfc  = (const float*)d_in[8];
    const float* bfc  = (const float*)d_in[9];
    float* out = (float*)d_out;

    cudaFuncSetAttribute(fused_igo_mma, cudaFuncAttributeMaxDynamicSharedMemorySize, F_SMEM);
    cudaFuncSetAttribute(wout_update,   cudaFuncAttributeMaxDynamicSharedMemorySize, U_SMEM);

    w2h_kernel<<<(4 * HID * HID + 255) / 256, 256>>>(Wi, Wg, Wo, Wout);
    copy_z_kernel<<<(BATCH * HID + 255) / 256, 256>>>(y);
    softmaxdot_kernel<<<BATCH, 256>>>(Wfc, bfc, out);

    dim3 fgrid(BATCH / BM, HID / BN);   // 32 x 4 = 128 CTAs
    for (int t = 0; t < TSTEPS - 1; ++t) {
        fused_igo_mma<<<fgrid, 512, F_SMEM>>>();
        wout_update<<<BATCH / BM2, 256, U_SMEM>>>(bout, ts, Wfc, bfc, out, t);
    }
}